// round 14
// baseline (speedup 1.0000x reference)
#include <cuda_runtime.h>
#include <cuda_bf16.h>
#include <cuda_fp16.h>
#include <math.h>
#include <stdint.h>

typedef unsigned long long ull;

// Problem constants
#define B 32
#define S 2048
#define H 1024
#define M_TOTAL (B * S)
#define UA_GROUPS (H * H / 8)

// ---------------------------------------------------------------------------
// Scratch (no allocations allowed -> __device__ globals)
// ---------------------------------------------------------------------------
__device__ float g_qp[B * H];            // q_proj + Wa_b + Ua_b
__device__ float g_spart[8 * M_TOTAL];   // per-n-tile partial scores
__device__ float g_cpart[8 * B * H];     // per-s-chunk partial context
__device__ __half g_ua_h[H * H];         // fp16 Ua (2 MB)

// ---------------------------------------------------------------------------
// Asm helpers (base-target-safe: ldmatrix / mma.sync / cp.async, sm_80+)
// ---------------------------------------------------------------------------
__device__ __forceinline__ uint32_t smem_u32(const void* p) {
    uint32_t a;
    asm("{ .reg .u64 t; cvta.to.shared.u64 t, %1; cvt.u32.u64 %0, t; }"
        : "=r"(a) : "l"(p));
    return a;
}

__device__ __forceinline__ void cpa16(uint32_t dst, const void* src) {
    asm volatile("cp.async.cg.shared.global [%0], [%1], 16;"
                 :: "r"(dst), "l"(src) : "memory");
}
#define CP_COMMIT() asm volatile("cp.async.commit_group;" ::: "memory")
#define CP_WAIT1()  asm volatile("cp.async.wait_group 1;" ::: "memory")

#define LDSM_X4(r, addr)                                                      \
    asm volatile("ldmatrix.sync.aligned.m8n8.x4.shared.b16 {%0,%1,%2,%3}, [%4];" \
                 : "=r"((r)[0]), "=r"((r)[1]), "=r"((r)[2]), "=r"((r)[3])     \
                 : "r"(addr))

#define MMAF16(d, a, bq)                                                      \
    asm volatile("mma.sync.aligned.m16n8k16.row.col.f32.f16.f16.f32 "         \
                 "{%0,%1,%2,%3}, {%4,%5,%6,%7}, {%8,%9}, {%0,%1,%2,%3};"      \
                 : "+f"((d)[0]), "+f"((d)[1]), "+f"((d)[2]), "+f"((d)[3])     \
                 : "r"((a)[0]), "r"((a)[1]), "r"((a)[2]), "r"((a)[3]),        \
                   "r"((bq)[0]), "r"((bq)[1]))

// pack two fp32 -> f16x2 register (low = x)
__device__ __forceinline__ uint32_t pkh2(float x, float y) {
    __half2 h = __floats2half2_rn(x, y);
    return *(uint32_t*)&h;
}

// ---------------------------------------------------------------------------
// K0: fp32 -> fp16 prepass for Ua_w only (keys stay fp32; K2 converts inline)
// ---------------------------------------------------------------------------
__global__ void k0_cvt(const float* __restrict__ ua) {
    size_t idx = (size_t)blockIdx.x * blockDim.x + threadIdx.x;
    float4 a = ((const float4*)ua)[idx * 2];
    float4 b = ((const float4*)ua)[idx * 2 + 1];
    __half2 h0 = __floats2half2_rn(a.x, a.y);
    __half2 h1 = __floats2half2_rn(a.z, a.w);
    __half2 h2 = __floats2half2_rn(b.x, b.y);
    __half2 h3 = __floats2half2_rn(b.z, b.w);
    uint4 out;
    out.x = *(uint32_t*)&h0;
    out.y = *(uint32_t*)&h1;
    out.z = *(uint32_t*)&h2;
    out.w = *(uint32_t*)&h3;
    ((uint4*)g_ua_h)[idx] = out;
}

// ---------------------------------------------------------------------------
// K1: q_proj[b][o] = query[b,:] . Wa_w[o,:] + Wa_b[o] + Ua_b[o]
// grid (8 o-chunks, 16 b-pairs) x 256 threads. Wa read once from DRAM.
// ---------------------------------------------------------------------------
__global__ void k1_qproj(const float* __restrict__ query,
                         const float* __restrict__ Wa_w,
                         const float* __restrict__ Wa_b,
                         const float* __restrict__ Ua_b) {
    __shared__ float sq[2 * H];
    const int tid = threadIdx.x;
    const int b0 = blockIdx.y * 2;

#pragma unroll
    for (int i = 0; i < 2; ++i) {
        const int idx = tid + i * 256;               // 0..511 float4 slots
        ((float4*)sq)[idx] = ((const float4*)(query + b0 * H))[idx];
    }
    __syncthreads();

    const int o  = blockIdx.x * 128 + (tid >> 1);
    const int k0 = (tid & 1) * 512;
    const float4* wr = (const float4*)(Wa_w + (size_t)o * H + k0);
    const float4* q0 = (const float4*)(sq + k0);
    const float4* q1 = (const float4*)(sq + H + k0);

    float a0 = 0.f, a1 = 0.f;
#pragma unroll 8
    for (int i = 0; i < 128; ++i) {
        float4 w = wr[i];
        float4 x = q0[i];
        float4 y = q1[i];
        a0 += w.x * x.x + w.y * x.y + w.z * x.z + w.w * x.w;
        a1 += w.x * y.x + w.y * y.y + w.z * y.z + w.w * y.w;
    }
    a0 += __shfl_xor_sync(0xFFFFFFFFu, a0, 1);
    a1 += __shfl_xor_sync(0xFFFFFFFFu, a1, 1);
    if ((tid & 1) == 0) {
        const float bias = Wa_b[o] + Ua_b[o];
        g_qp[b0 * H + o] = a0 + bias;
        g_qp[(b0 + 1) * H + o] = a1 + bias;
    }
}

// ---------------------------------------------------------------------------
// K2: fp16 mma.sync GEMM; A (keys) staged as fp32 via cp.async and converted
//     to fragments with LDS.64 + cvt (no keys prepass). B (Ua) fp16 + ldmatrix.
// CTA 128x128, K chunk 64, 512 threads, warp tile 32x32, 3-stage cp.async.
// grid = (8 n-tiles, 512 m-tiles).
// ---------------------------------------------------------------------------
#define NC 16                        // 1024 / 64 k-chunks
#define A_ROW_B 272                  // 64 fp32 = 256B, padded to 272 (17x16B)
#define A_TILE_B (128 * A_ROW_B)     // 34816
#define B_TILE_B 16384               // 128 rows x 128B (64 fp16)
#define STAGE_B (A_TILE_B + B_TILE_B)  // 51200
#define NSTAGE 3
#define SM_RED (NSTAGE * STAGE_B)    // 153600: 128 x 16 floats (8KB)
#define SM_VA (SM_RED + 8192)
#define SM_QP (SM_VA + 512)
#define K2_SMEM (SM_QP + 512)        // 162816 B

__global__ __launch_bounds__(512, 1)
void k2_mma(const float* __restrict__ keys,
            const float* __restrict__ Va_w) {
    extern __shared__ char smem[];
    const uint32_t sb = smem_u32(smem);
    const int tid = threadIdx.x;
    const int lane = tid & 31;
    const int wid = tid >> 5;
    const int warp_m = wid >> 2;          // 0..3 (32 rows each)
    const int warp_n = wid & 3;           // 0..3 (32 cols each)
    const int n0 = blockIdx.x * 128;
    const int m0 = blockIdx.y * 128;
    const int b  = blockIdx.y >> 4;       // 16 m-tiles per batch

    // epilogue constants into smem (consumed after mainloop)
    if (tid < 128) {
        ((float*)(smem + SM_VA))[tid] = Va_w[n0 + tid];
        ((float*)(smem + SM_QP))[tid] = g_qp[b * H + n0 + tid];
    }

    // A loader: 4 threads per row, 4 granules (16B = 4 fp32) each
    const int arow = tid >> 2;            // 0..127
    const int ag = tid & 3;               // granule group
    const float* Ag = keys + (size_t)(m0 + arow) * H;
    uint32_t aswa[4];
#pragma unroll
    for (int j = 0; j < 4; ++j)
        aswa[j] = (uint32_t)arow * A_ROW_B + (uint32_t)(ag * 4 + j) * 16;

    // B loader: 4 threads per row, 2 granules (16B = 8 fp16) each
    const __half* Bg = g_ua_h + (size_t)(n0 + arow) * H;
    uint32_t bsw[2];
#pragma unroll
    for (int j = 0; j < 2; ++j)
        bsw[j] = (uint32_t)arow * 128 +
                 (((uint32_t)(ag * 2 + j) ^ (arow & 7)) << 4);

    float acc[2][4][4];
#pragma unroll
    for (int i = 0; i < 2; ++i)
#pragma unroll
        for (int j = 0; j < 4; ++j)
#pragma unroll
            for (int k = 0; k < 4; ++k) acc[i][j][k] = 0.f;

    // ---- prologue: issue stages 0 and 1 ----
#pragma unroll
    for (int s = 0; s < 2; ++s) {
        const uint32_t st = sb + s * STAGE_B;
        const int k0 = s * 64;
#pragma unroll
        for (int j = 0; j < 4; ++j)
            cpa16(st + aswa[j], Ag + k0 + (ag * 4 + j) * 4);
#pragma unroll
        for (int j = 0; j < 2; ++j)
            cpa16(st + A_TILE_B + bsw[j], Bg + k0 + (ag * 2 + j) * 8);
        CP_COMMIT();
    }

    // per-thread fragment coordinates
    const int fr = lane >> 2;             // fragment row within 8
    const int fc = (lane & 3) * 2;        // fragment col pair base

    // ---- mainloop ----
    int stage_c = 0;
    for (int c = 0; c < NC; ++c) {
        CP_WAIT1();
        __syncthreads();

        // issue chunk c+2 into the stage just freed
        if (c + 2 < NC) {
            int sn = stage_c + 2;
            if (sn >= NSTAGE) sn -= NSTAGE;
            const uint32_t st = sb + sn * STAGE_B;
            const int k0 = (c + 2) * 64;
#pragma unroll
            for (int j = 0; j < 4; ++j)
                cpa16(st + aswa[j], Ag + k0 + (ag * 4 + j) * 4);
#pragma unroll
            for (int j = 0; j < 2; ++j)
                cpa16(st + A_TILE_B + bsw[j], Bg + k0 + (ag * 2 + j) * 8);
        }
        CP_COMMIT();

        const uint32_t curA = sb + stage_c * STAGE_B;
        const uint32_t curB = curA + A_TILE_B;
        const char* smA = smem + (stage_c * STAGE_B);

#pragma unroll
        for (int ks = 0; ks < 4; ++ks) {
            // A fragments via LDS.64 + cvt (fp32 smem, padded rows)
            uint32_t ah[2][4];
#pragma unroll
            for (int fm = 0; fm < 2; ++fm) {
                const int r = warp_m * 32 + fm * 16 + fr;
                const int col = ks * 16 + fc;
                const float* base = (const float*)(smA + r * A_ROW_B) + col;
                const float* base8 = (const float*)(smA + (r + 8) * A_ROW_B) + col;
                float2 v0 = *(const float2*)(base);        // (r, c)
                float2 v1 = *(const float2*)(base8);       // (r+8, c)
                float2 v2 = *(const float2*)(base + 8);    // (r, c+8)
                float2 v3 = *(const float2*)(base8 + 8);   // (r+8, c+8)
                ah[fm][0] = pkh2(v0.x, v0.y);
                ah[fm][1] = pkh2(v1.x, v1.y);
                ah[fm][2] = pkh2(v2.x, v2.y);
                ah[fm][3] = pkh2(v3.x, v3.y);
            }
            // B fragments: 2 x LDSM_X4, each = two n8 blocks x two k-halves
            uint32_t bh[4][2];
#pragma unroll
            for (int fn2 = 0; fn2 < 2; ++fn2) {
                const int q = lane >> 3;
                const int fn_loc = fn2 * 2 + (q >> 1);
                const int kh = q & 1;
                const int rn = warp_n * 32 + fn_loc * 8 + (lane & 7);
                const int ch = ks * 2 + kh;
                const uint32_t bd = curB + (uint32_t)rn * 128 +
                                    (((uint32_t)(ch ^ (rn & 7))) << 4);
                uint32_t r[4];
                LDSM_X4(r, bd);
                bh[fn2 * 2 + 0][0] = r[0];
                bh[fn2 * 2 + 0][1] = r[1];
                bh[fn2 * 2 + 1][0] = r[2];
                bh[fn2 * 2 + 1][1] = r[3];
            }
#pragma unroll
            for (int fm = 0; fm < 2; ++fm) {
#pragma unroll
                for (int fn = 0; fn < 4; ++fn) {
                    MMAF16(acc[fm][fn], ah[fm], bh[fn]);
                }
            }
        }
        stage_c = (stage_c + 1 == NSTAGE) ? 0 : stage_c + 1;
    }

    // ---- fused epilogue: tanh + Va dot, reduce over columns ----
    const float* sva = (const float*)(smem + SM_VA);
    const float* sqp = (const float*)(smem + SM_QP);
    float* red = (float*)(smem + SM_RED);
    const int quad = lane & 3;
    const int ln4 = lane >> 2;
    const int slot = warp_n * 4 + quad;

    __syncthreads();

#pragma unroll
    for (int fm = 0; fm < 2; ++fm) {
        float rv0 = 0.f, rv1 = 0.f;
#pragma unroll
        for (int fn = 0; fn < 4; ++fn) {
            const int c0 = warp_n * 32 + fn * 8 + quad * 2;
            const int c1 = c0 + 1;
            rv0 += sva[c0] * tanhf(acc[fm][fn][0] + sqp[c0]);
            rv0 += sva[c1] * tanhf(acc[fm][fn][1] + sqp[c1]);
            rv1 += sva[c0] * tanhf(acc[fm][fn][2] + sqp[c0]);
            rv1 += sva[c1] * tanhf(acc[fm][fn][3] + sqp[c1]);
        }
        const int rowA = warp_m * 32 + fm * 16 + ln4;
        red[rowA * 16 + slot] = rv0;
        red[(rowA + 8) * 16 + slot] = rv1;
    }
    __syncthreads();
    if (tid < 128) {
        float s = 0.f;
#pragma unroll
        for (int t = 0; t < 16; ++t) s += red[tid * 16 + t];
        g_spart[(size_t)blockIdx.x * M_TOTAL + m0 + tid] = s;
    }
}

// ---------------------------------------------------------------------------
// K3: reduce 8 partials per row + softmax -> weights
// ---------------------------------------------------------------------------
__global__ void k3_softmax(float* __restrict__ wout) {
    __shared__ float sm[256];
    const int b = blockIdx.x;
    const int tid = threadIdx.x;

    float v[8];
#pragma unroll
    for (int i = 0; i < 8; ++i) {
        int s = tid + i * 256;
        float t = 0.f;
#pragma unroll
        for (int p = 0; p < 8; ++p)
            t += g_spart[(size_t)p * M_TOTAL + b * S + s];
        v[i] = t;
    }
    float mx = v[0];
#pragma unroll
    for (int i = 1; i < 8; ++i) mx = fmaxf(mx, v[i]);
    sm[tid] = mx;
    __syncthreads();
    for (int off = 128; off; off >>= 1) {
        if (tid < off) sm[tid] = fmaxf(sm[tid], sm[tid + off]);
        __syncthreads();
    }
    mx = sm[0];
    __syncthreads();
    float sum = 0.f;
#pragma unroll
    for (int i = 0; i < 8; ++i) {
        v[i] = expf(v[i] - mx);
        sum += v[i];
    }
    sm[tid] = sum;
    __syncthreads();
    for (int off = 128; off; off >>= 1) {
        if (tid < off) sm[tid] += sm[tid + off];
        __syncthreads();
    }
    float inv = 1.0f / sm[0];
#pragma unroll
    for (int i = 0; i < 8; ++i)
        wout[b * S + tid + i * 256] = v[i] * inv;
}

// ---------------------------------------------------------------------------
// K4: partial context GEMV on fp32 keys, 8 s-chunks of 256.
// grid (B, H/128, 8), 128 threads; one h-column per thread, 256 s-iters.
// ---------------------------------------------------------------------------
__global__ void k4_context(const float* __restrict__ keys,
                           const float* __restrict__ w) {
    const int b  = blockIdx.x;
    const int hc = blockIdx.y;
    const int sc = blockIdx.z;
    const int h  = hc * 128 + threadIdx.x;
    const float* kb = keys + ((size_t)b * S + sc * 256) * H + h;
    const float* wb = w + b * S + sc * 256;
    float acc = 0.f;
#pragma unroll 8
    for (int s = 0; s < 256; ++s)
        acc += wb[s] * kb[(size_t)s * H];
    g_cpart[sc * (B * H) + b * H + h] = acc;
}

// ---------------------------------------------------------------------------
// K5: reduce 8 context partials
// ---------------------------------------------------------------------------
__global__ void k5_reduce(float* __restrict__ ctx) {
    int i = blockIdx.x * 256 + threadIdx.x;
    float s = 0.f;
#pragma unroll
    for (int p = 0; p < 8; ++p)
        s += g_cpart[p * (B * H) + i];
    ctx[i] = s;
}

// ---------------------------------------------------------------------------
// launch
// ---------------------------------------------------------------------------
extern "C" void kernel_launch(void* const* d_in, const int* in_sizes, int n_in,
                              void* d_out, int out_size) {
    const float* query = (const float*)d_in[0];
    const float* keys  = (const float*)d_in[1];
    const float* Wa_w  = (const float*)d_in[2];
    const float* Wa_b  = (const float*)d_in[3];
    const float* Ua_w  = (const float*)d_in[4];
    const float* Ua_b  = (const float*)d_in[5];
    const float* Va_w  = (const float*)d_in[6];
    // Va_b (d_in[7]) softmax-invariant; idx (d_in[8]) unused.

    float* out = (float*)d_out;
    float* ctx_out = out;             // (B,1,H)
    float* w_out   = out + B * H;     // (B,1,S)

    cudaFuncSetAttribute(k2_mma, cudaFuncAttributeMaxDynamicSharedMemorySize,
                         K2_SMEM);

    // K0: Ua fp32 -> fp16 (tiny)
    k0_cvt<<<UA_GROUPS / 256, 256>>>(Ua_w);

    dim3 g1(8, 16);
    k1_qproj<<<g1, 256>>>(query, Wa_w, Wa_b, Ua_b);

    dim3 g2(8, 512);
    k2_mma<<<g2, 512, K2_SMEM>>>(keys, Va_w);

    k3_softmax<<<B, 256>>>(w_out);

    dim3 g4(B, H / 128, 8);
    k4_context<<<g4, 128>>>(keys, w_out);
    k5_reduce<<<(B * H) / 256, 256>>>(ctx_out);
}

// round 15
// speedup vs baseline: 1.2257x; 1.2257x over previous
#include <cuda_runtime.h>
#include <cuda_bf16.h>
#include <cuda_fp16.h>
#include <math.h>
#include <stdint.h>

typedef unsigned long long ull;

// Problem constants
#define B 32
#define S 2048
#define H 1024
#define M_TOTAL (B * S)
#define UA_GROUPS (H * H / 8)

// ---------------------------------------------------------------------------
// Scratch (no allocations allowed -> __device__ globals)
// ---------------------------------------------------------------------------
__device__ float g_qp[B * H];            // q_proj + Wa_b + Ua_b
__device__ float g_spart[8 * M_TOTAL];   // per-n-tile partial scores
__device__ float g_cpart[16 * B * H];    // per-s-chunk partial context (2 MB)
__device__ __half g_ua_h[H * H];         // fp16 Ua (2 MB)

// ---------------------------------------------------------------------------
// Asm helpers (base-target-safe: ldmatrix / mma.sync / cp.async, sm_80+)
// ---------------------------------------------------------------------------
__device__ __forceinline__ uint32_t smem_u32(const void* p) {
    uint32_t a;
    asm("{ .reg .u64 t; cvta.to.shared.u64 t, %1; cvt.u32.u64 %0, t; }"
        : "=r"(a) : "l"(p));
    return a;
}

__device__ __forceinline__ void cpa16(uint32_t dst, const void* src) {
    asm volatile("cp.async.cg.shared.global [%0], [%1], 16;"
                 :: "r"(dst), "l"(src) : "memory");
}
#define CP_COMMIT() asm volatile("cp.async.commit_group;" ::: "memory")
#define CP_WAIT1()  asm volatile("cp.async.wait_group 1;" ::: "memory")

#define STS128(smem_addr, v)                                                  \
    asm volatile("st.shared.v4.b32 [%0], {%1,%2,%3,%4};"                      \
                 :: "r"(smem_addr), "r"((v).x), "r"((v).y), "r"((v).z),       \
                    "r"((v).w) : "memory")

#define LDSM_X4(r, addr)                                                      \
    asm volatile("ldmatrix.sync.aligned.m8n8.x4.shared.b16 {%0,%1,%2,%3}, [%4];" \
                 : "=r"((r)[0]), "=r"((r)[1]), "=r"((r)[2]), "=r"((r)[3])     \
                 : "r"(addr))

#define MMAF16(d, a, bq)                                                      \
    asm volatile("mma.sync.aligned.m16n8k16.row.col.f32.f16.f16.f32 "         \
                 "{%0,%1,%2,%3}, {%4,%5,%6,%7}, {%8,%9}, {%0,%1,%2,%3};"      \
                 : "+f"((d)[0]), "+f"((d)[1]), "+f"((d)[2]), "+f"((d)[3])     \
                 : "r"((a)[0]), "r"((a)[1]), "r"((a)[2]), "r"((a)[3]),        \
                   "r"((bq)[0]), "r"((bq)[1]))

__device__ __forceinline__ uint32_t pkh2(float x, float y) {
    __half2 h = __floats2half2_rn(x, y);
    return *(uint32_t*)&h;
}

// pack 8 fp32 (two float4) -> uint4 of f16x2
__device__ __forceinline__ uint4 pk8(float4 a, float4 b) {
    uint4 o;
    o.x = pkh2(a.x, a.y);
    o.y = pkh2(a.z, a.w);
    o.z = pkh2(b.x, b.y);
    o.w = pkh2(b.z, b.w);
    return o;
}

// ---------------------------------------------------------------------------
// K0: fp32 -> fp16 prepass for Ua_w only (keys converted inside K2)
// ---------------------------------------------------------------------------
__global__ void k0_cvt(const float* __restrict__ ua) {
    size_t idx = (size_t)blockIdx.x * blockDim.x + threadIdx.x;
    float4 a = ((const float4*)ua)[idx * 2];
    float4 b = ((const float4*)ua)[idx * 2 + 1];
    uint4 out = pk8(a, b);
    ((uint4*)g_ua_h)[idx] = out;
}

// ---------------------------------------------------------------------------
// K1: q_proj[b][o] = query[b,:] . Wa_w[o,:] + Wa_b[o] + Ua_b[o]
// ---------------------------------------------------------------------------
__global__ void k1_qproj(const float* __restrict__ query,
                         const float* __restrict__ Wa_w,
                         const float* __restrict__ Wa_b,
                         const float* __restrict__ Ua_b) {
    __shared__ float sq[2 * H];
    const int tid = threadIdx.x;
    const int b0 = blockIdx.y * 2;

#pragma unroll
    for (int i = 0; i < 2; ++i) {
        const int idx = tid + i * 256;
        ((float4*)sq)[idx] = ((const float4*)(query + b0 * H))[idx];
    }
    __syncthreads();

    const int o  = blockIdx.x * 128 + (tid >> 1);
    const int k0 = (tid & 1) * 512;
    const float4* wr = (const float4*)(Wa_w + (size_t)o * H + k0);
    const float4* q0 = (const float4*)(sq + k0);
    const float4* q1 = (const float4*)(sq + H + k0);

    float a0 = 0.f, a1 = 0.f;
#pragma unroll 8
    for (int i = 0; i < 128; ++i) {
        float4 w = wr[i];
        float4 x = q0[i];
        float4 y = q1[i];
        a0 += w.x * x.x + w.y * x.y + w.z * x.z + w.w * x.w;
        a1 += w.x * y.x + w.y * y.y + w.z * y.z + w.w * y.w;
    }
    a0 += __shfl_xor_sync(0xFFFFFFFFu, a0, 1);
    a1 += __shfl_xor_sync(0xFFFFFFFFu, a1, 1);
    if ((tid & 1) == 0) {
        const float bias = Wa_b[o] + Ua_b[o];
        g_qp[b0 * H + o] = a0 + bias;
        g_qp[(b0 + 1) * H + o] = a1 + bias;
    }
}

// ---------------------------------------------------------------------------
// K2: fp16 mma.sync GEMM. A (keys fp32) staged via 3-stage cp.async, then
//     per-ELEMENT converted (LDS.128 + pack + STS.128, spread over ks) into a
//     double-buffered fp16 tile consumed by ldmatrix. No keys prepass.
// CTA 128x128, K chunk 64, 512 threads, warp tile 32x32.
// grid = (8 n-tiles, 512 m-tiles).
// ---------------------------------------------------------------------------
#define NC 16
#define A32_ROW_B 272                    // 64 fp32 = 256B, padded to 272
#define A32_TILE_B (128 * A32_ROW_B)     // 34816
#define B16_TILE_B 16384
#define NSTAGE 3
#define SM_B16 (NSTAGE * A32_TILE_B)     // 104448
#define SM_A16 (SM_B16 + NSTAGE * B16_TILE_B)   // 153600 (2 x 16384)
#define SM_RED (SM_A16 + 2 * 16384)      // 186368 (128 x 16 floats)
#define SM_VA (SM_RED + 8192)            // 194560
#define SM_QP (SM_VA + 512)              // 195072
#define K2_SMEM (SM_QP + 512)            // 195584 B

__global__ __launch_bounds__(512, 1)
void k2_mma(const float* __restrict__ keys,
            const float* __restrict__ Va_w) {
    extern __shared__ char smem[];
    const uint32_t sb = smem_u32(smem);
    const int tid = threadIdx.x;
    const int lane = tid & 31;
    const int wid = tid >> 5;
    const int warp_m = wid >> 2;          // 0..3 (32 rows each)
    const int warp_n = wid & 3;           // 0..3 (32 cols each)
    const int n0 = blockIdx.x * 128;
    const int m0 = blockIdx.y * 128;
    const int b  = blockIdx.y >> 4;

    if (tid < 128) {
        ((float*)(smem + SM_VA))[tid] = Va_w[n0 + tid];
        ((float*)(smem + SM_QP))[tid] = g_qp[b * H + n0 + tid];
    }

    // loader indexing: 4 threads per row
    const int arow = tid >> 2;            // 0..127
    const int ag = tid & 3;               // 0..3
    const float* Ag = keys + (size_t)(m0 + arow) * H;
    const __half* Bg = g_ua_h + (size_t)(n0 + arow) * H;
    // A fp32 smem offsets: granules 4ag..4ag+3 (16 floats, columns 16ag..+15)
    const uint32_t a32base = (uint32_t)arow * A32_ROW_B + (uint32_t)ag * 64;
    // fp16 A output: granules 2ag, 2ag+1 (swizzled)
    const uint32_t a16o0 = (uint32_t)arow * 128 +
                           (((uint32_t)(2 * ag + 0) ^ (arow & 7)) << 4);
    const uint32_t a16o1 = (uint32_t)arow * 128 +
                           (((uint32_t)(2 * ag + 1) ^ (arow & 7)) << 4);
    // B fp16 smem offsets
    uint32_t bsw[2];
#pragma unroll
    for (int j = 0; j < 2; ++j)
        bsw[j] = (uint32_t)arow * 128 +
                 (((uint32_t)(2 * ag + j) ^ (arow & 7)) << 4);

    float acc[2][4][4];
#pragma unroll
    for (int i = 0; i < 2; ++i)
#pragma unroll
        for (int j = 0; j < 4; ++j)
#pragma unroll
            for (int k = 0; k < 4; ++k) acc[i][j][k] = 0.f;

    // ---- issue helper offsets (A fp32: 4 granules; B fp16: 2 granules) ----
    // prologue: stages 0 (chunk 0) and 1 (chunk 1)
#pragma unroll
    for (int s = 0; s < 2; ++s) {
        const int k0 = s * 64;
#pragma unroll
        for (int j = 0; j < 4; ++j)
            cpa16(sb + s * A32_TILE_B + a32base + j * 16,
                  Ag + k0 + (4 * ag + j) * 4);
#pragma unroll
        for (int j = 0; j < 2; ++j)
            cpa16(sb + SM_B16 + s * B16_TILE_B + bsw[j],
                  Bg + k0 + (2 * ag + j) * 8);
        CP_COMMIT();
    }
    CP_WAIT1();         // stage 0 landed
    __syncthreads();

    // convert chunk 0: fp32 stage 0 -> fp16 buffer 0
    {
        const char* src = smem + a32base;
        float4 t0 = *(const float4*)(src);
        float4 t1 = *(const float4*)(src + 16);
        float4 t2 = *(const float4*)(src + 32);
        float4 t3 = *(const float4*)(src + 48);
        uint4 u0 = pk8(t0, t1);
        uint4 u1 = pk8(t2, t3);
        STS128(sb + SM_A16 + a16o0, u0);
        STS128(sb + SM_A16 + a16o1, u1);
    }
    __syncthreads();

    // ---- mainloop ----
    int stage_c = 0;
    for (int c = 0; c < NC; ++c) {
        // issue chunk c+2 into stage (c+2)%NSTAGE (freed >=1 sync ago)
        if (c + 2 < NC) {
            int sn = stage_c + 2;
            if (sn >= NSTAGE) sn -= NSTAGE;
            const int k0 = (c + 2) * 64;
#pragma unroll
            for (int j = 0; j < 4; ++j)
                cpa16(sb + sn * A32_TILE_B + a32base + j * 16,
                      Ag + k0 + (4 * ag + j) * 4);
#pragma unroll
            for (int j = 0; j < 2; ++j)
                cpa16(sb + SM_B16 + sn * B16_TILE_B + bsw[j],
                      Bg + k0 + (2 * ag + j) * 8);
        }
        CP_COMMIT();
        CP_WAIT1();     // groups up to (c+1) landed -> stage c+1 resident

        int sn1 = stage_c + 1;
        if (sn1 >= NSTAGE) sn1 -= NSTAGE;
        const char* cvsrc = smem + sn1 * A32_TILE_B + a32base;
        const uint32_t cvdst = sb + SM_A16 + ((c + 1) & 1) * 16384;
        const bool conv = (c + 1 < NC);

        const uint32_t curA16 = sb + SM_A16 + (c & 1) * 16384;
        const uint32_t curB = sb + SM_B16 + stage_c * B16_TILE_B;

        float4 t0, t1, t2, t3;
#pragma unroll
        for (int ks = 0; ks < 4; ++ks) {
            // A fragments: 2 x LDSM_X4 from fp16 A buffer
            uint32_t ah[2][4];
#pragma unroll
            for (int fm = 0; fm < 2; ++fm) {
                const int row = warp_m * 32 + fm * 16 + (lane & 15);
                const int ch = ks * 2 + (lane >> 4);
                const uint32_t ad = curA16 + (uint32_t)row * 128 +
                                    (((uint32_t)(ch ^ (row & 7))) << 4);
                LDSM_X4(ah[fm], ad);
            }
            // B fragments: 2 x LDSM_X4, each = two n8 blocks x two k-halves
            uint32_t bh[4][2];
#pragma unroll
            for (int fn2 = 0; fn2 < 2; ++fn2) {
                const int q = lane >> 3;
                const int fn_loc = fn2 * 2 + (q >> 1);
                const int kh = q & 1;
                const int rn = warp_n * 32 + fn_loc * 8 + (lane & 7);
                const int ch = ks * 2 + kh;
                const uint32_t bd = curB + (uint32_t)rn * 128 +
                                    (((uint32_t)(ch ^ (rn & 7))) << 4);
                uint32_t r[4];
                LDSM_X4(r, bd);
                bh[fn2 * 2 + 0][0] = r[0];
                bh[fn2 * 2 + 0][1] = r[1];
                bh[fn2 * 2 + 1][0] = r[2];
                bh[fn2 * 2 + 1][1] = r[3];
            }
#pragma unroll
            for (int fm = 0; fm < 2; ++fm) {
#pragma unroll
                for (int fn = 0; fn < 4; ++fn) {
                    MMAF16(acc[fm][fn], ah[fm], bh[fn]);
                }
            }

            // per-element conversion of chunk c+1, spread across quarters
            if (conv) {
                if (ks == 0) {
                    t0 = *(const float4*)(cvsrc);
                    t1 = *(const float4*)(cvsrc + 16);
                } else if (ks == 1) {
                    uint4 u = pk8(t0, t1);
                    STS128(cvdst + a16o0, u);
                } else if (ks == 2) {
                    t2 = *(const float4*)(cvsrc + 32);
                    t3 = *(const float4*)(cvsrc + 48);
                } else {
                    uint4 u = pk8(t2, t3);
                    STS128(cvdst + a16o1, u);
                }
            }
        }
        __syncthreads();   // fp16[c+1] complete; stage reads done
        stage_c = (stage_c + 1 == NSTAGE) ? 0 : stage_c + 1;
    }

    // ---- fused epilogue: tanh + Va dot, reduce over columns ----
    const float* sva = (const float*)(smem + SM_VA);
    const float* sqp = (const float*)(smem + SM_QP);
    float* red = (float*)(smem + SM_RED);
    const int quad = lane & 3;
    const int ln4 = lane >> 2;
    const int slot = warp_n * 4 + quad;

#pragma unroll
    for (int fm = 0; fm < 2; ++fm) {
        float rv0 = 0.f, rv1 = 0.f;
#pragma unroll
        for (int fn = 0; fn < 4; ++fn) {
            const int c0 = warp_n * 32 + fn * 8 + quad * 2;
            const int c1 = c0 + 1;
            rv0 += sva[c0] * tanhf(acc[fm][fn][0] + sqp[c0]);
            rv0 += sva[c1] * tanhf(acc[fm][fn][1] + sqp[c1]);
            rv1 += sva[c0] * tanhf(acc[fm][fn][2] + sqp[c0]);
            rv1 += sva[c1] * tanhf(acc[fm][fn][3] + sqp[c1]);
        }
        const int rowA = warp_m * 32 + fm * 16 + ln4;
        red[rowA * 16 + slot] = rv0;
        red[(rowA + 8) * 16 + slot] = rv1;
    }
    __syncthreads();
    if (tid < 128) {
        float s = 0.f;
#pragma unroll
        for (int t = 0; t < 16; ++t) s += red[tid * 16 + t];
        g_spart[(size_t)blockIdx.x * M_TOTAL + m0 + tid] = s;
    }
}

// ---------------------------------------------------------------------------
// K3: reduce 8 partials per row + softmax -> weights
// ---------------------------------------------------------------------------
__global__ void k3_softmax(float* __restrict__ wout) {
    __shared__ float sm[256];
    const int b = blockIdx.x;
    const int tid = threadIdx.x;

    float v[8];
#pragma unroll
    for (int i = 0; i < 8; ++i) {
        int s = tid + i * 256;
        float t = 0.f;
#pragma unroll
        for (int p = 0; p < 8; ++p)
            t += g_spart[(size_t)p * M_TOTAL + b * S + s];
        v[i] = t;
    }
    float mx = v[0];
#pragma unroll
    for (int i = 1; i < 8; ++i) mx = fmaxf(mx, v[i]);
    sm[tid] = mx;
    __syncthreads();
    for (int off = 128; off; off >>= 1) {
        if (tid < off) sm[tid] = fmaxf(sm[tid], sm[tid + off]);
        __syncthreads();
    }
    mx = sm[0];
    __syncthreads();
    float sum = 0.f;
#pragma unroll
    for (int i = 0; i < 8; ++i) {
        v[i] = expf(v[i] - mx);
        sum += v[i];
    }
    sm[tid] = sum;
    __syncthreads();
    for (int off = 128; off; off >>= 1) {
        if (tid < off) sm[tid] += sm[tid + off];
        __syncthreads();
    }
    float inv = 1.0f / sm[0];
#pragma unroll
    for (int i = 0; i < 8; ++i)
        wout[b * S + tid + i * 256] = v[i] * inv;
}

// ---------------------------------------------------------------------------
// K4: partial context GEMV on fp32 keys, float4 per thread, 16 s-chunks.
// grid (B, 2, 16), 128 threads; 4 h-columns per thread, 128 s-iters.
// ---------------------------------------------------------------------------
__global__ void k4_context(const float* __restrict__ keys,
                           const float* __restrict__ w) {
    const int b  = blockIdx.x;
    const int hq = blockIdx.y;
    const int sc = blockIdx.z;
    const int h  = hq * 512 + threadIdx.x * 4;
    const float* kb = keys + ((size_t)b * S + sc * 128) * H + h;
    const float* wb = w + b * S + sc * 128;
    float a0 = 0.f, a1 = 0.f, a2 = 0.f, a3 = 0.f;
#pragma unroll 8
    for (int s = 0; s < 128; ++s) {
        float4 kv = *(const float4*)(kb + (size_t)s * H);
        float ws = wb[s];
        a0 += ws * kv.x;
        a1 += ws * kv.y;
        a2 += ws * kv.z;
        a3 += ws * kv.w;
    }
    float* dst = g_cpart + sc * (B * H) + b * H + h;
    dst[0] = a0; dst[1] = a1; dst[2] = a2; dst[3] = a3;
}

// ---------------------------------------------------------------------------
// K5: reduce 16 context partials
// ---------------------------------------------------------------------------
__global__ void k5_reduce(float* __restrict__ ctx) {
    int i = blockIdx.x * 256 + threadIdx.x;
    float s = 0.f;
#pragma unroll
    for (int p = 0; p < 16; ++p)
        s += g_cpart[p * (B * H) + i];
    ctx[i] = s;
}

// ---------------------------------------------------------------------------
// launch
// ---------------------------------------------------------------------------
extern "C" void kernel_launch(void* const* d_in, const int* in_sizes, int n_in,
                              void* d_out, int out_size) {
    const float* query = (const float*)d_in[0];
    const float* keys  = (const float*)d_in[1];
    const float* Wa_w  = (const float*)d_in[2];
    const float* Wa_b  = (const float*)d_in[3];
    const float* Ua_w  = (const float*)d_in[4];
    const float* Ua_b  = (const float*)d_in[5];
    const float* Va_w  = (const float*)d_in[6];
    // Va_b (d_in[7]) softmax-invariant; idx (d_in[8]) unused.

    float* out = (float*)d_out;
    float* ctx_out = out;             // (B,1,H)
    float* w_out   = out + B * H;     // (B,1,S)

    cudaFuncSetAttribute(k2_mma, cudaFuncAttributeMaxDynamicSharedMemorySize,
                         K2_SMEM);

    // K0: Ua fp32 -> fp16 (tiny)
    k0_cvt<<<UA_GROUPS / 256, 256>>>(Ua_w);

    dim3 g1(8, 16);
    k1_qproj<<<g1, 256>>>(query, Wa_w, Wa_b, Ua_b);

    dim3 g2(8, 512);
    k2_mma<<<g2, 512, K2_SMEM>>>(keys, Va_w);

    k3_softmax<<<B, 256>>>(w_out);

    dim3 g4(B, 2, 16);
    k4_context<<<g4, 128>>>(keys, w_out);
    k5_reduce<<<(B * H) / 256, 256>>>(ctx_out);
}

// round 16
// speedup vs baseline: 1.3491x; 1.1007x over previous
#include <cuda_runtime.h>
#include <cuda_bf16.h>
#include <cuda_fp16.h>
#include <math.h>
#include <stdint.h>

typedef unsigned long long ull;

// Problem constants
#define B 32
#define S 2048
#define H 1024
#define M_TOTAL (B * S)
#define KEY_GROUPS (B * S * H / 8)     // 8-elem conversion groups for keys
#define UA_GROUPS (H * H / 8)

// ---------------------------------------------------------------------------
// Scratch (no allocations allowed -> __device__ globals)
// ---------------------------------------------------------------------------
__device__ float g_qp[B * H];            // q_proj + Wa_b + Ua_b
__device__ float g_spart[8 * M_TOTAL];   // per-n-tile partial scores
__device__ float g_cpart[16 * B * H];    // per-s-chunk partial context
__device__ __half g_keys_h[(size_t)B * S * H];   // fp16 keys (128 MB)
__device__ __half g_ua_h[H * H];                 // fp16 Ua (2 MB)

// ---------------------------------------------------------------------------
// Asm helpers (base-target-safe: ldmatrix / mma.sync / cp.async, sm_80+)
// ---------------------------------------------------------------------------
__device__ __forceinline__ uint32_t smem_u32(const void* p) {
    uint32_t a;
    asm("{ .reg .u64 t; cvta.to.shared.u64 t, %1; cvt.u32.u64 %0, t; }"
        : "=r"(a) : "l"(p));
    return a;
}

__device__ __forceinline__ void cpa16(uint32_t dst, const void* src) {
    asm volatile("cp.async.cg.shared.global [%0], [%1], 16;"
                 :: "r"(dst), "l"(src) : "memory");
}
#define CP_COMMIT() asm volatile("cp.async.commit_group;" ::: "memory")
#define CP_WAIT1()  asm volatile("cp.async.wait_group 1;" ::: "memory")

#define LDSM_X4(r, addr)                                                      \
    asm volatile("ldmatrix.sync.aligned.m8n8.x4.shared.b16 {%0,%1,%2,%3}, [%4];" \
                 : "=r"((r)[0]), "=r"((r)[1]), "=r"((r)[2]), "=r"((r)[3])     \
                 : "r"(addr))

#define MMAF16(d, a, bq)                                                      \
    asm volatile("mma.sync.aligned.m16n8k16.row.col.f32.f16.f16.f32 "         \
                 "{%0,%1,%2,%3}, {%4,%5,%6,%7}, {%8,%9}, {%0,%1,%2,%3};"      \
                 : "+f"((d)[0]), "+f"((d)[1]), "+f"((d)[2]), "+f"((d)[3])     \
                 : "r"((a)[0]), "r"((a)[1]), "r"((a)[2]), "r"((a)[3]),        \
                   "r"((bq)[0]), "r"((bq)[1]))

// ---------------------------------------------------------------------------
// K0: fp32 -> fp16 prepass for keys and Ua_w (8 elems / thread, 16B stores)
// ---------------------------------------------------------------------------
__global__ void k0_cvt(const float* __restrict__ keys,
                       const float* __restrict__ ua) {
    size_t g = (size_t)blockIdx.x * blockDim.x + threadIdx.x;
    const float* src;
    __half* dst;
    size_t idx;
    if (g < KEY_GROUPS) {
        src = keys; dst = g_keys_h; idx = g;
    } else {
        src = ua; dst = g_ua_h; idx = g - KEY_GROUPS;
    }
    float4 a = ((const float4*)src)[idx * 2];
    float4 b = ((const float4*)src)[idx * 2 + 1];
    __half2 h0 = __floats2half2_rn(a.x, a.y);
    __half2 h1 = __floats2half2_rn(a.z, a.w);
    __half2 h2 = __floats2half2_rn(b.x, b.y);
    __half2 h3 = __floats2half2_rn(b.z, b.w);
    uint4 out;
    out.x = *(uint32_t*)&h0;
    out.y = *(uint32_t*)&h1;
    out.z = *(uint32_t*)&h2;
    out.w = *(uint32_t*)&h3;
    ((uint4*)dst)[idx] = out;
}

// ---------------------------------------------------------------------------
// K1: q_proj[b][o] = query[b,:] . Wa_w[o,:] + Wa_b[o] + Ua_b[o]
// grid (8 o-chunks, 16 b-pairs) x 256 threads. Wa read once from DRAM.
// ---------------------------------------------------------------------------
__global__ void k1_qproj(const float* __restrict__ query,
                         const float* __restrict__ Wa_w,
                         const float* __restrict__ Wa_b,
                         const float* __restrict__ Ua_b) {
    __shared__ float sq[2 * H];
    const int tid = threadIdx.x;
    const int b0 = blockIdx.y * 2;

#pragma unroll
    for (int i = 0; i < 2; ++i) {
        const int idx = tid + i * 256;
        ((float4*)sq)[idx] = ((const float4*)(query + b0 * H))[idx];
    }
    __syncthreads();

    const int o  = blockIdx.x * 128 + (tid >> 1);
    const int k0 = (tid & 1) * 512;
    const float4* wr = (const float4*)(Wa_w + (size_t)o * H + k0);
    const float4* q0 = (const float4*)(sq + k0);
    const float4* q1 = (const float4*)(sq + H + k0);

    float a0 = 0.f, a1 = 0.f;
#pragma unroll 8
    for (int i = 0; i < 128; ++i) {
        float4 w = wr[i];
        float4 x = q0[i];
        float4 y = q1[i];
        a0 += w.x * x.x + w.y * x.y + w.z * x.z + w.w * x.w;
        a1 += w.x * y.x + w.y * y.y + w.z * y.z + w.w * y.w;
    }
    a0 += __shfl_xor_sync(0xFFFFFFFFu, a0, 1);
    a1 += __shfl_xor_sync(0xFFFFFFFFu, a1, 1);
    if ((tid & 1) == 0) {
        const float bias = Wa_b[o] + Ua_b[o];
        g_qp[b0 * H + o] = a0 + bias;
        g_qp[(b0 + 1) * H + o] = a1 + bias;
    }
}

// ---------------------------------------------------------------------------
// K2: single-term fp16 mma.sync GEMM, cp.async 3-stage pipeline,
//     fused tanh/Va epilogue. CTA 128x128, K chunk 64, 256 threads,
//     8 warps, warp tile 64x32, 2 CTAs/SM. grid = (8 n-tiles, 512 m-tiles).
//     (Known-good R13 configuration — unchanged.)
// ---------------------------------------------------------------------------
#define NC 16                      // 1024 / 64 k-chunks
#define TILE_B 16384               // 128 rows x 128B (64 fp16)
#define STAGE_B (2 * TILE_B)       // A, B  (32 KB)
#define NSTAGE 3
#define SM_RED (NSTAGE * STAGE_B)  // 98304: 128 x 16 floats (8KB)
#define SM_VA (SM_RED + 8192)
#define SM_QP (SM_VA + 512)
#define K2_SMEM (SM_QP + 512)      // 107520 B

__global__ __launch_bounds__(256, 2)
void k2_mma(const float* __restrict__ Va_w) {
    extern __shared__ char smem[];
    const uint32_t sb = smem_u32(smem);
    const int tid = threadIdx.x;
    const int lane = tid & 31;
    const int wid = tid >> 5;
    const int warp_m = wid >> 2;          // 0..1 (64 rows each)
    const int warp_n = wid & 3;           // 0..3 (32 cols each)
    const int n0 = blockIdx.x * 128;
    const int m0 = blockIdx.y * 128;
    const int b  = blockIdx.y >> 4;       // 16 m-tiles per batch

    // epilogue constants into smem (consumed after mainloop)
    if (tid < 128) {
        ((float*)(smem + SM_VA))[tid] = Va_w[n0 + tid];
        ((float*)(smem + SM_QP))[tid] = g_qp[b * H + n0 + tid];
    }

    // loader indexing: 2 threads per row, 4 granules (16B = 8 fp16) each
    const int lrow = tid >> 1;            // 0..127
    const int g0 = (tid & 1) * 4;         // 0 or 4
    const __half* Ag = g_keys_h + (size_t)(m0 + lrow) * H;
    const __half* Bg = g_ua_h + (size_t)(n0 + lrow) * H;
    uint32_t sw[4];
#pragma unroll
    for (int j = 0; j < 4; ++j)
        sw[j] = (uint32_t)lrow * 128 + (((uint32_t)(g0 + j) ^ (lrow & 7)) << 4);

    float acc[4][4][4];
#pragma unroll
    for (int i = 0; i < 4; ++i)
#pragma unroll
        for (int j = 0; j < 4; ++j)
#pragma unroll
            for (int k = 0; k < 4; ++k) acc[i][j][k] = 0.f;

    // ---- prologue: issue stages 0 and 1 ----
#pragma unroll
    for (int s = 0; s < 2; ++s) {
        const uint32_t st = sb + s * STAGE_B;
        const int k0 = s * 64;
#pragma unroll
        for (int j = 0; j < 4; ++j) {
            cpa16(st + sw[j], Ag + k0 + (g0 + j) * 8);
            cpa16(st + TILE_B + sw[j], Bg + k0 + (g0 + j) * 8);
        }
        CP_COMMIT();
    }

    // ---- mainloop ----
    int stage_c = 0;   // stage index of chunk c
    for (int c = 0; c < NC; ++c) {
        CP_WAIT1();                 // stage c landed (pending <= 1)
        __syncthreads();            // all warps done with stage c-1 reads

        // issue chunk c+2 into the stage just freed
        if (c + 2 < NC) {
            int sn = stage_c + 2;
            if (sn >= NSTAGE) sn -= NSTAGE;
            const uint32_t st = sb + sn * STAGE_B;
            const int k0 = (c + 2) * 64;
#pragma unroll
            for (int j = 0; j < 4; ++j) {
                cpa16(st + sw[j], Ag + k0 + (g0 + j) * 8);
                cpa16(st + TILE_B + sw[j], Bg + k0 + (g0 + j) * 8);
            }
        }
        CP_COMMIT();                // commit (possibly empty) keeps count fixed

        const uint32_t cur = sb + stage_c * STAGE_B;
#pragma unroll
        for (int ks = 0; ks < 4; ++ks) {
            // A fragments: 4 x LDSM_X4 (64 rows x k16)
            uint32_t ah[4][4];
#pragma unroll
            for (int fm = 0; fm < 4; ++fm) {
                const int row = warp_m * 64 + fm * 16 + (lane & 15);
                const int ch = ks * 2 + (lane >> 4);
                const uint32_t ad = cur + (uint32_t)row * 128 +
                                    (((uint32_t)(ch ^ (row & 7))) << 4);
                LDSM_X4(ah[fm], ad);
            }
            // B fragments: 2 x LDSM_X4, each covering two n8 blocks
            uint32_t bh[4][2];
#pragma unroll
            for (int fn2 = 0; fn2 < 2; ++fn2) {
                const int fn_loc = fn2 * 2 + (lane >> 4);         // n8 block
                const int kh = (lane >> 3) & 1;                    // k half
                const int rn = warp_n * 32 + fn_loc * 8 + (lane & 7);
                const int ch = ks * 2 + kh;
                const uint32_t bd = cur + TILE_B + (uint32_t)rn * 128 +
                                    (((uint32_t)(ch ^ (rn & 7))) << 4);
                uint32_t r[4];
                LDSM_X4(r, bd);
                bh[fn2 * 2 + 0][0] = r[0];
                bh[fn2 * 2 + 0][1] = r[1];
                bh[fn2 * 2 + 1][0] = r[2];
                bh[fn2 * 2 + 1][1] = r[3];
            }
#pragma unroll
            for (int fm = 0; fm < 4; ++fm) {
#pragma unroll
                for (int fn = 0; fn < 4; ++fn) {
                    MMAF16(acc[fm][fn], ah[fm], bh[fn]);
                }
            }
        }
        stage_c = (stage_c + 1 == NSTAGE) ? 0 : stage_c + 1;
    }

    // ---- fused epilogue: tanh + Va dot, reduce over columns ----
    const float* sva = (const float*)(smem + SM_VA);
    const float* sqp = (const float*)(smem + SM_QP);
    float* red = (float*)(smem + SM_RED);
    const int quad = lane & 3;
    const int ln4 = lane >> 2;
    const int slot = warp_n * 4 + quad;

    __syncthreads();   // mainloop reads finished

#pragma unroll
    for (int fm = 0; fm < 4; ++fm) {
        float rv0 = 0.f, rv1 = 0.f;
#pragma unroll
        for (int fn = 0; fn < 4; ++fn) {
            const int c0 = warp_n * 32 + fn * 8 + quad * 2;
            const int c1 = c0 + 1;
            rv0 += sva[c0] * tanhf(acc[fm][fn][0] + sqp[c0]);
            rv0 += sva[c1] * tanhf(acc[fm][fn][1] + sqp[c1]);
            rv1 += sva[c0] * tanhf(acc[fm][fn][2] + sqp[c0]);
            rv1 += sva[c1] * tanhf(acc[fm][fn][3] + sqp[c1]);
        }
        const int rowA = warp_m * 64 + fm * 16 + ln4;
        red[rowA * 16 + slot] = rv0;
        red[(rowA + 8) * 16 + slot] = rv1;
    }
    __syncthreads();
    if (tid < 128) {
        float s = 0.f;
#pragma unroll
        for (int t = 0; t < 16; ++t) s += red[tid * 16 + t];
        g_spart[(size_t)blockIdx.x * M_TOTAL + m0 + tid] = s;
    }
}

// ---------------------------------------------------------------------------
// K3: reduce 8 partials per row + softmax -> weights (512 threads for MLP)
// ---------------------------------------------------------------------------
__global__ void k3_softmax(float* __restrict__ wout) {
    __shared__ float sm[512];
    const int b = blockIdx.x;
    const int tid = threadIdx.x;

    float v[4];
#pragma unroll
    for (int i = 0; i < 4; ++i) {
        int s = tid + i * 512;
        float t = 0.f;
#pragma unroll
        for (int p = 0; p < 8; ++p)
            t += g_spart[(size_t)p * M_TOTAL + b * S + s];
        v[i] = t;
    }
    float mx = fmaxf(fmaxf(v[0], v[1]), fmaxf(v[2], v[3]));
    sm[tid] = mx;
    __syncthreads();
    for (int off = 256; off; off >>= 1) {
        if (tid < off) sm[tid] = fmaxf(sm[tid], sm[tid + off]);
        __syncthreads();
    }
    mx = sm[0];
    __syncthreads();
    float sum = 0.f;
#pragma unroll
    for (int i = 0; i < 4; ++i) {
        v[i] = expf(v[i] - mx);
        sum += v[i];
    }
    sm[tid] = sum;
    __syncthreads();
    for (int off = 256; off; off >>= 1) {
        if (tid < off) sm[tid] += sm[tid + off];
        __syncthreads();
    }
    float inv = 1.0f / sm[0];
#pragma unroll
    for (int i = 0; i < 4; ++i)
        wout[b * S + tid + i * 512] = v[i] * inv;
}

// ---------------------------------------------------------------------------
// K4: partial context GEMV on fp16 keys, uint4 loads (8 fp16 per thread),
//     16 s-chunks. grid (B, 16), 128 threads; thread covers 8 h-columns.
// ---------------------------------------------------------------------------
__global__ void k4_context(const float* __restrict__ w) {
    const int b  = blockIdx.x;
    const int sc = blockIdx.y;
    const int h0 = threadIdx.x * 8;                  // 8 h-columns
    const __half* kb = g_keys_h + ((size_t)b * S + sc * 128) * H + h0;
    const float* wb = w + b * S + sc * 128;
    float a[8];
#pragma unroll
    for (int i = 0; i < 8; ++i) a[i] = 0.f;
#pragma unroll 4
    for (int s = 0; s < 128; ++s) {
        uint4 raw = *(const uint4*)(kb + (size_t)s * H);
        float ws = wb[s];
        float2 f0 = __half22float2(*(__half2*)&raw.x);
        float2 f1 = __half22float2(*(__half2*)&raw.y);
        float2 f2 = __half22float2(*(__half2*)&raw.z);
        float2 f3 = __half22float2(*(__half2*)&raw.w);
        a[0] += ws * f0.x; a[1] += ws * f0.y;
        a[2] += ws * f1.x; a[3] += ws * f1.y;
        a[4] += ws * f2.x; a[5] += ws * f2.y;
        a[6] += ws * f3.x; a[7] += ws * f3.y;
    }
    float* dst = g_cpart + sc * (B * H) + b * H + h0;
#pragma unroll
    for (int i = 0; i < 8; ++i) dst[i] = a[i];
}

// ---------------------------------------------------------------------------
// K5: reduce 16 context partials
// ---------------------------------------------------------------------------
__global__ void k5_reduce(float* __restrict__ ctx) {
    int i = blockIdx.x * 256 + threadIdx.x;
    float s = 0.f;
#pragma unroll
    for (int p = 0; p < 16; ++p)
        s += g_cpart[p * (B * H) + i];
    ctx[i] = s;
}

// ---------------------------------------------------------------------------
// launch
// ---------------------------------------------------------------------------
extern "C" void kernel_launch(void* const* d_in, const int* in_sizes, int n_in,
                              void* d_out, int out_size) {
    const float* query = (const float*)d_in[0];
    const float* keys  = (const float*)d_in[1];
    const float* Wa_w  = (const float*)d_in[2];
    const float* Wa_b  = (const float*)d_in[3];
    const float* Ua_w  = (const float*)d_in[4];
    const float* Ua_b  = (const float*)d_in[5];
    const float* Va_w  = (const float*)d_in[6];
    // Va_b (d_in[7]) softmax-invariant; idx (d_in[8]) unused.

    float* out = (float*)d_out;
    float* ctx_out = out;             // (B,1,H)
    float* w_out   = out + B * H;     // (B,1,S)

    cudaFuncSetAttribute(k2_mma, cudaFuncAttributeMaxDynamicSharedMemorySize,
                         K2_SMEM);

    // K0: fp32 -> fp16 prepass (keys + Ua)
    k0_cvt<<<(KEY_GROUPS + UA_GROUPS) / 256, 256>>>(keys, Ua_w);

    dim3 g1(8, 16);
    k1_qproj<<<g1, 256>>>(query, Wa_w, Wa_b, Ua_b);

    dim3 g2(8, 512);
    k2_mma<<<g2, 256, K2_SMEM>>>(Va_w);

    k3_softmax<<<B, 512>>>(w_out);

    dim3 g4(B, 16);
    k4_context<<<g4, 128>>>(w_out);
    k5_reduce<<<(B * H) / 256, 256>>>(ctx_out);
}

// round 17
// speedup vs baseline: 2.0211x; 1.4981x over previous
#include <cuda_runtime.h>
#include <cuda_bf16.h>
#include <cuda_fp16.h>
#include <math.h>
#include <stdint.h>

typedef unsigned long long ull;

// Problem constants
#define B 32
#define S 2048
#define H 1024
#define M_TOTAL (B * S)
#define KEY_GROUPS (B * S * H / 8)     // 8-elem conversion groups for keys
#define UA_GROUPS (H * H / 8)

// ---------------------------------------------------------------------------
// Scratch (no allocations allowed -> __device__ globals)
// ---------------------------------------------------------------------------
__device__ float g_qp[B * H];            // q_proj + Wa_b + Ua_b
__device__ float g_spart[8 * M_TOTAL];   // per-n-tile partial scores
__device__ float g_cpart[16 * B * H];    // per-s-chunk partial context
__device__ __half g_keys_h[(size_t)B * S * H];   // fp16 keys (128 MB)
__device__ __half g_ua_h[H * H];                 // fp16 Ua (2 MB)

// ---------------------------------------------------------------------------
// Asm helpers (base-target-safe: ldmatrix / mma.sync / cp.async, sm_80+)
// ---------------------------------------------------------------------------
__device__ __forceinline__ uint32_t smem_u32(const void* p) {
    uint32_t a;
    asm("{ .reg .u64 t; cvta.to.shared.u64 t, %1; cvt.u32.u64 %0, t; }"
        : "=r"(a) : "l"(p));
    return a;
}

__device__ __forceinline__ void cpa16(uint32_t dst, const void* src) {
    asm volatile("cp.async.cg.shared.global [%0], [%1], 16;"
                 :: "r"(dst), "l"(src) : "memory");
}
#define CP_COMMIT() asm volatile("cp.async.commit_group;" ::: "memory")
#define CP_WAIT1()  asm volatile("cp.async.wait_group 1;" ::: "memory")

#define LDSM_X4(r, addr)                                                      \
    asm volatile("ldmatrix.sync.aligned.m8n8.x4.shared.b16 {%0,%1,%2,%3}, [%4];" \
                 : "=r"((r)[0]), "=r"((r)[1]), "=r"((r)[2]), "=r"((r)[3])     \
                 : "r"(addr))

#define MMAF16(d, a, bq)                                                      \
    asm volatile("mma.sync.aligned.m16n8k16.row.col.f32.f16.f16.f32 "         \
                 "{%0,%1,%2,%3}, {%4,%5,%6,%7}, {%8,%9}, {%0,%1,%2,%3};"      \
                 : "+f"((d)[0]), "+f"((d)[1]), "+f"((d)[2]), "+f"((d)[3])     \
                 : "r"((a)[0]), "r"((a)[1]), "r"((a)[2]), "r"((a)[3]),        \
                   "r"((bq)[0]), "r"((bq)[1]))

// ---------------------------------------------------------------------------
// K0: fp32 -> fp16 prepass for keys and Ua_w (8 elems / thread, 16B stores)
// ---------------------------------------------------------------------------
__global__ void k0_cvt(const float* __restrict__ keys,
                       const float* __restrict__ ua) {
    size_t g = (size_t)blockIdx.x * blockDim.x + threadIdx.x;
    const float* src;
    __half* dst;
    size_t idx;
    if (g < KEY_GROUPS) {
        src = keys; dst = g_keys_h; idx = g;
    } else {
        src = ua; dst = g_ua_h; idx = g - KEY_GROUPS;
    }
    float4 a = ((const float4*)src)[idx * 2];
    float4 b = ((const float4*)src)[idx * 2 + 1];
    __half2 h0 = __floats2half2_rn(a.x, a.y);
    __half2 h1 = __floats2half2_rn(a.z, a.w);
    __half2 h2 = __floats2half2_rn(b.x, b.y);
    __half2 h3 = __floats2half2_rn(b.z, b.w);
    uint4 out;
    out.x = *(uint32_t*)&h0;
    out.y = *(uint32_t*)&h1;
    out.z = *(uint32_t*)&h2;
    out.w = *(uint32_t*)&h3;
    ((uint4*)dst)[idx] = out;
}

// ---------------------------------------------------------------------------
// K1: q_proj[b][o] = query[b,:] . Wa_w[o,:] + Wa_b[o] + Ua_b[o]
// grid (8 o-chunks, 16 b-pairs) x 256 threads. Wa read once from DRAM.
// ---------------------------------------------------------------------------
__global__ void k1_qproj(const float* __restrict__ query,
                         const float* __restrict__ Wa_w,
                         const float* __restrict__ Wa_b,
                         const float* __restrict__ Ua_b) {
    __shared__ float sq[2 * H];
    const int tid = threadIdx.x;
    const int b0 = blockIdx.y * 2;

#pragma unroll
    for (int i = 0; i < 2; ++i) {
        const int idx = tid + i * 256;               // 0..511 float4 slots
        ((float4*)sq)[idx] = ((const float4*)(query + b0 * H))[idx];
    }
    __syncthreads();

    const int o  = blockIdx.x * 128 + (tid >> 1);
    const int k0 = (tid & 1) * 512;
    const float4* wr = (const float4*)(Wa_w + (size_t)o * H + k0);
    const float4* q0 = (const float4*)(sq + k0);
    const float4* q1 = (const float4*)(sq + H + k0);

    float a0 = 0.f, a1 = 0.f;
#pragma unroll 8
    for (int i = 0; i < 128; ++i) {
        float4 w = wr[i];
        float4 x = q0[i];
        float4 y = q1[i];
        a0 += w.x * x.x + w.y * x.y + w.z * x.z + w.w * x.w;
        a1 += w.x * y.x + w.y * y.y + w.z * y.z + w.w * y.w;
    }
    a0 += __shfl_xor_sync(0xFFFFFFFFu, a0, 1);
    a1 += __shfl_xor_sync(0xFFFFFFFFu, a1, 1);
    if ((tid & 1) == 0) {
        const float bias = Wa_b[o] + Ua_b[o];
        g_qp[b0 * H + o] = a0 + bias;
        g_qp[(b0 + 1) * H + o] = a1 + bias;
    }
}

// ---------------------------------------------------------------------------
// K2: single-term fp16 mma.sync GEMM, cp.async 3-stage pipeline,
//     fused tanh/Va epilogue. CTA 128x128, K chunk 64, 256 threads,
//     8 warps, warp tile 64x32, 2 CTAs/SM. grid = (8 n-tiles, 512 m-tiles).
//     (Known-good R13 configuration — unchanged.)
// ---------------------------------------------------------------------------
#define NC 16                      // 1024 / 64 k-chunks
#define TILE_B 16384               // 128 rows x 128B (64 fp16)
#define STAGE_B (2 * TILE_B)       // A, B  (32 KB)
#define NSTAGE 3
#define SM_RED (NSTAGE * STAGE_B)  // 98304: 128 x 16 floats (8KB)
#define SM_VA (SM_RED + 8192)
#define SM_QP (SM_VA + 512)
#define K2_SMEM (SM_QP + 512)      // 107520 B

__global__ __launch_bounds__(256, 2)
void k2_mma(const float* __restrict__ Va_w) {
    extern __shared__ char smem[];
    const uint32_t sb = smem_u32(smem);
    const int tid = threadIdx.x;
    const int lane = tid & 31;
    const int wid = tid >> 5;
    const int warp_m = wid >> 2;          // 0..1 (64 rows each)
    const int warp_n = wid & 3;           // 0..3 (32 cols each)
    const int n0 = blockIdx.x * 128;
    const int m0 = blockIdx.y * 128;
    const int b  = blockIdx.y >> 4;       // 16 m-tiles per batch

    // epilogue constants into smem (consumed after mainloop)
    if (tid < 128) {
        ((float*)(smem + SM_VA))[tid] = Va_w[n0 + tid];
        ((float*)(smem + SM_QP))[tid] = g_qp[b * H + n0 + tid];
    }

    // loader indexing: 2 threads per row, 4 granules (16B = 8 fp16) each
    const int lrow = tid >> 1;            // 0..127
    const int g0 = (tid & 1) * 4;         // 0 or 4
    const __half* Ag = g_keys_h + (size_t)(m0 + lrow) * H;
    const __half* Bg = g_ua_h + (size_t)(n0 + lrow) * H;
    uint32_t sw[4];
#pragma unroll
    for (int j = 0; j < 4; ++j)
        sw[j] = (uint32_t)lrow * 128 + (((uint32_t)(g0 + j) ^ (lrow & 7)) << 4);

    float acc[4][4][4];
#pragma unroll
    for (int i = 0; i < 4; ++i)
#pragma unroll
        for (int j = 0; j < 4; ++j)
#pragma unroll
            for (int k = 0; k < 4; ++k) acc[i][j][k] = 0.f;

    // ---- prologue: issue stages 0 and 1 ----
#pragma unroll
    for (int s = 0; s < 2; ++s) {
        const uint32_t st = sb + s * STAGE_B;
        const int k0 = s * 64;
#pragma unroll
        for (int j = 0; j < 4; ++j) {
            cpa16(st + sw[j], Ag + k0 + (g0 + j) * 8);
            cpa16(st + TILE_B + sw[j], Bg + k0 + (g0 + j) * 8);
        }
        CP_COMMIT();
    }

    // ---- mainloop ----
    int stage_c = 0;   // stage index of chunk c
    for (int c = 0; c < NC; ++c) {
        CP_WAIT1();                 // stage c landed (pending <= 1)
        __syncthreads();            // all warps done with stage c-1 reads

        // issue chunk c+2 into the stage just freed
        if (c + 2 < NC) {
            int sn = stage_c + 2;
            if (sn >= NSTAGE) sn -= NSTAGE;
            const uint32_t st = sb + sn * STAGE_B;
            const int k0 = (c + 2) * 64;
#pragma unroll
            for (int j = 0; j < 4; ++j) {
                cpa16(st + sw[j], Ag + k0 + (g0 + j) * 8);
                cpa16(st + TILE_B + sw[j], Bg + k0 + (g0 + j) * 8);
            }
        }
        CP_COMMIT();                // commit (possibly empty) keeps count fixed

        const uint32_t cur = sb + stage_c * STAGE_B;
#pragma unroll
        for (int ks = 0; ks < 4; ++ks) {
            // A fragments: 4 x LDSM_X4 (64 rows x k16)
            uint32_t ah[4][4];
#pragma unroll
            for (int fm = 0; fm < 4; ++fm) {
                const int row = warp_m * 64 + fm * 16 + (lane & 15);
                const int ch = ks * 2 + (lane >> 4);
                const uint32_t ad = cur + (uint32_t)row * 128 +
                                    (((uint32_t)(ch ^ (row & 7))) << 4);
                LDSM_X4(ah[fm], ad);
            }
            // B fragments: 2 x LDSM_X4, each covering two n8 blocks
            uint32_t bh[4][2];
#pragma unroll
            for (int fn2 = 0; fn2 < 2; ++fn2) {
                const int fn_loc = fn2 * 2 + (lane >> 4);         // n8 block
                const int kh = (lane >> 3) & 1;                    // k half
                const int rn = warp_n * 32 + fn_loc * 8 + (lane & 7);
                const int ch = ks * 2 + kh;
                const uint32_t bd = cur + TILE_B + (uint32_t)rn * 128 +
                                    (((uint32_t)(ch ^ (rn & 7))) << 4);
                uint32_t r[4];
                LDSM_X4(r, bd);
                bh[fn2 * 2 + 0][0] = r[0];
                bh[fn2 * 2 + 0][1] = r[1];
                bh[fn2 * 2 + 1][0] = r[2];
                bh[fn2 * 2 + 1][1] = r[3];
            }
#pragma unroll
            for (int fm = 0; fm < 4; ++fm) {
#pragma unroll
                for (int fn = 0; fn < 4; ++fn) {
                    MMAF16(acc[fm][fn], ah[fm], bh[fn]);
                }
            }
        }
        stage_c = (stage_c + 1 == NSTAGE) ? 0 : stage_c + 1;
    }

    // ---- fused epilogue: tanh + Va dot, reduce over columns ----
    const float* sva = (const float*)(smem + SM_VA);
    const float* sqp = (const float*)(smem + SM_QP);
    float* red = (float*)(smem + SM_RED);
    const int quad = lane & 3;
    const int ln4 = lane >> 2;
    const int slot = warp_n * 4 + quad;

    __syncthreads();   // mainloop reads finished

#pragma unroll
    for (int fm = 0; fm < 4; ++fm) {
        float rv0 = 0.f, rv1 = 0.f;
#pragma unroll
        for (int fn = 0; fn < 4; ++fn) {
            const int c0 = warp_n * 32 + fn * 8 + quad * 2;
            const int c1 = c0 + 1;
            rv0 += sva[c0] * tanhf(acc[fm][fn][0] + sqp[c0]);
            rv0 += sva[c1] * tanhf(acc[fm][fn][1] + sqp[c1]);
            rv1 += sva[c0] * tanhf(acc[fm][fn][2] + sqp[c0]);
            rv1 += sva[c1] * tanhf(acc[fm][fn][3] + sqp[c1]);
        }
        const int rowA = warp_m * 64 + fm * 16 + ln4;
        red[rowA * 16 + slot] = rv0;
        red[(rowA + 8) * 16 + slot] = rv1;
    }
    __syncthreads();
    if (tid < 128) {
        float s = 0.f;
#pragma unroll
        for (int t = 0; t < 16; ++t) s += red[tid * 16 + t];
        g_spart[(size_t)blockIdx.x * M_TOTAL + m0 + tid] = s;
    }
}

// ---------------------------------------------------------------------------
// K3: reduce 8 partials per row + softmax -> weights
// ---------------------------------------------------------------------------
__global__ void k3_softmax(float* __restrict__ wout) {
    __shared__ float sm[256];
    const int b = blockIdx.x;
    const int tid = threadIdx.x;

    float v[8];
#pragma unroll
    for (int i = 0; i < 8; ++i) {
        int s = tid + i * 256;
        float t = 0.f;
#pragma unroll
        for (int p = 0; p < 8; ++p)
            t += g_spart[(size_t)p * M_TOTAL + b * S + s];
        v[i] = t;
    }
    float mx = v[0];
#pragma unroll
    for (int i = 1; i < 8; ++i) mx = fmaxf(mx, v[i]);
    sm[tid] = mx;
    __syncthreads();
    for (int off = 128; off; off >>= 1) {
        if (tid < off) sm[tid] = fmaxf(sm[tid], sm[tid + off]);
        __syncthreads();
    }
    mx = sm[0];
    __syncthreads();
    float sum = 0.f;
#pragma unroll
    for (int i = 0; i < 8; ++i) {
        v[i] = expf(v[i] - mx);
        sum += v[i];
    }
    sm[tid] = sum;
    __syncthreads();
    for (int off = 128; off; off >>= 1) {
        if (tid < off) sm[tid] += sm[tid + off];
        __syncthreads();
    }
    float inv = 1.0f / sm[0];
#pragma unroll
    for (int i = 0; i < 8; ++i)
        wout[b * S + tid + i * 256] = v[i] * inv;
}

// ---------------------------------------------------------------------------
// K4: partial context GEMV on fp16 keys, 16 s-chunks of 128 for parallelism.
// grid (B, H/256, 16), 128 threads; each thread 2 h-columns, 128 s-iters.
// (Same proven body as R13; only the z-split doubled.)
// ---------------------------------------------------------------------------
__global__ void k4_context(const float* __restrict__ w) {
    const int b  = blockIdx.x;
    const int hc = blockIdx.y;
    const int sc = blockIdx.z;
    const int h2 = hc * 128 + threadIdx.x;          // half2 column index
    const __half2* kb = (const __half2*)(g_keys_h +
                        ((size_t)b * S + sc * 128) * H) + h2;
    const float* wb = w + b * S + sc * 128;
    float a0 = 0.f, a1 = 0.f;
#pragma unroll 8
    for (int s = 0; s < 128; ++s) {
        float2 kv = __half22float2(kb[(size_t)s * (H / 2)]);
        float ws = wb[s];
        a0 += ws * kv.x;
        a1 += ws * kv.y;
    }
    float* dst = g_cpart + sc * (B * H) + b * H + h2 * 2;
    dst[0] = a0;
    dst[1] = a1;
}

// ---------------------------------------------------------------------------
// K5: reduce 16 context partials
// ---------------------------------------------------------------------------
__global__ void k5_reduce(float* __restrict__ ctx) {
    int i = blockIdx.x * 256 + threadIdx.x;
    float s = 0.f;
#pragma unroll
    for (int p = 0; p < 16; ++p)
        s += g_cpart[p * (B * H) + i];
    ctx[i] = s;
}

// ---------------------------------------------------------------------------
// launch
// ---------------------------------------------------------------------------
extern "C" void kernel_launch(void* const* d_in, const int* in_sizes, int n_in,
                              void* d_out, int out_size) {
    const float* query = (const float*)d_in[0];
    const float* keys  = (const float*)d_in[1];
    const float* Wa_w  = (const float*)d_in[2];
    const float* Wa_b  = (const float*)d_in[3];
    const float* Ua_w  = (const float*)d_in[4];
    const float* Ua_b  = (const float*)d_in[5];
    const float* Va_w  = (const float*)d_in[6];
    // Va_b (d_in[7]) softmax-invariant; idx (d_in[8]) unused.

    float* out = (float*)d_out;
    float* ctx_out = out;             // (B,1,H)
    float* w_out   = out + B * H;     // (B,1,S)

    cudaFuncSetAttribute(k2_mma, cudaFuncAttributeMaxDynamicSharedMemorySize,
                         K2_SMEM);

    // K0: fp32 -> fp16 prepass (keys + Ua)
    k0_cvt<<<(KEY_GROUPS + UA_GROUPS) / 256, 256>>>(keys, Ua_w);

    dim3 g1(8, 16);
    k1_qproj<<<g1, 256>>>(query, Wa_w, Wa_b, Ua_b);

    dim3 g2(8, 512);
    k2_mma<<<g2, 256, K2_SMEM>>>(Va_w);

    k3_softmax<<<B, 256>>>(w_out);

    dim3 g4(B, H / 256, 16);
    k4_context<<<g4, 128>>>(w_out);
    k5_reduce<<<(B * H) / 256, 256>>>(ctx_out);
}